// round 6
// baseline (speedup 1.0000x reference)
#include <cuda_runtime.h>
#include <cstdint>

#define MAX_NODES 100000
#define MAX_EDGES 1600000
#define F1 32
#define F2 16
#define F3 2
#define SEG 256
#define MAX_SEGN 512
#define TPB 256

// Scratch (device globals; no allocation allowed)
__device__ __align__(256) float g_y1[MAX_NODES * F1];
__device__ __align__(256) float g_h1[MAX_NODES * F1];
__device__ __align__(256) float g_y2[MAX_NODES * F2];
__device__ __align__(256) float g_h2[MAX_NODES * F2];
__device__ __align__(256) float g_y3[MAX_NODES * F3];
__device__ __align__(256) float g_h3[MAX_NODES * F3];

__device__ __align__(256) int g_cnt[MAX_NODES];      // in-degree histogram
__device__ __align__(256) int g_cur[MAX_NODES];      // fill cursor
__device__ __align__(256) int g_row[MAX_NODES + 1];  // CSR row offsets
__device__ __align__(256) int g_bsum[MAX_SEGN];      // scan spine (segment sums)
__device__ __align__(256) int g_srcs[MAX_EDGES];     // CSR columns (src ids)

// Grid barrier (count resets each barrier; gen monotonic across replays)
__device__ unsigned g_bar_cnt = 0;
__device__ volatile unsigned g_bar_gen = 0;

__device__ __forceinline__ void grid_sync() {
    __syncthreads();
    if (threadIdx.x == 0) {
        __threadfence();                           // release
        unsigned gen = g_bar_gen;
        unsigned arrived = atomicAdd(&g_bar_cnt, 1u);
        if (arrived == gridDim.x - 1) {
            g_bar_cnt = 0;
            __threadfence();
            g_bar_gen = gen + 1;                   // publish
        } else {
            while (g_bar_gen == gen) { }           // spin
            __threadfence();                       // acquire
        }
    }
    __syncthreads();
}

// ---- packed f32x2 helpers (ptxas never auto-fuses; PTX-only path) ----
__device__ __forceinline__ unsigned long long pack2(float lo, float hi) {
    unsigned long long r;
    asm("mov.b64 %0, {%1, %2};" : "=l"(r) : "f"(lo), "f"(hi));
    return r;
}
__device__ __forceinline__ void unpack2(unsigned long long v, float& lo, float& hi) {
    asm("mov.b64 {%0, %1}, %2;" : "=f"(lo), "=f"(hi) : "l"(v));
}
__device__ __forceinline__ unsigned long long ffma2(
    unsigned long long a, unsigned long long b, unsigned long long c) {
    unsigned long long d;
    asm("fma.rn.f32x2 %0, %1, %2, %3;" : "=l"(d) : "l"(a), "l"(b), "l"(c));
    return d;
}

// ---------------------------------------------------------------------------
// Transform: y = act(x) @ Wrel ; h = act(x) @ Wroot + b.
// Work item = (rel|root, output chunk of OCH, pair of nodes). NODES=2 halves
// SMEM weight traffic; fma.rn.f32x2 halves FMA issue + LDS instr count.
// ---------------------------------------------------------------------------
template <int FIN, int FOUT, bool RELU>
__device__ __forceinline__ void transform_phase(
    const float* __restrict__ x,
    const float* __restrict__ Wrel, const float* __restrict__ Wroot,
    const float* __restrict__ b,
    float* __restrict__ y, float* __restrict__ h,
    int n, float* s_w, int gtid, int T) {

    constexpr int OCH = (FOUT >= 8) ? 8 : FOUT;   // outputs per item
    constexpr int NCH = FOUT / OCH;               // chunks
    constexpr int P = OCH / 2;                    // f32x2 accumulator pairs
    constexpr int NODES = 2;

    for (int i = threadIdx.x; i < FIN * FOUT; i += blockDim.x) {
        s_w[i] = Wrel[i];
        s_w[FIN * FOUT + i] = Wroot[i];
    }
    for (int i = threadIdx.x; i < FOUT; i += blockDim.x)
        s_w[2 * FIN * FOUT + i] = b[i];
    __syncthreads();
    const float* s_b = s_w + 2 * FIN * FOUT;

    const int quads = (n + NODES - 1) / NODES;
    const int total = 2 * NCH * quads;
    for (int it = gtid; it < total; it += T) {
        const int q  = it % quads;
        const int sc = it / quads;
        const bool isRel = sc < NCH;
        const int chunk = isRel ? sc : sc - NCH;
        const int node0 = q * NODES;
        const bool has1 = (node0 + 1) < n;
        const float* W = (isRel ? s_w : s_w + FIN * FOUT) + chunk * OCH;

        unsigned long long acc0[P], acc1[P];
#pragma unroll
        for (int p = 0; p < P; p++) {
            unsigned long long init = isRel ? 0ull
                : pack2(s_b[chunk * OCH + 2 * p], s_b[chunk * OCH + 2 * p + 1]);
            acc0[p] = init;
            acc1[p] = init;
        }

        const float4* xr0 = reinterpret_cast<const float4*>(x + (size_t)node0 * FIN);
        const float4* xr1 = reinterpret_cast<const float4*>(x + (size_t)(node0 + 1) * FIN);
#pragma unroll
        for (int kk = 0; kk < FIN / 4; kk++) {
            float4 xv0 = __ldg(xr0 + kk);
            float4 xv1 = has1 ? __ldg(xr1 + kk) : make_float4(0.f, 0.f, 0.f, 0.f);
            float xs0[4] = {xv0.x, xv0.y, xv0.z, xv0.w};
            float xs1[4] = {xv1.x, xv1.y, xv1.z, xv1.w};
#pragma unroll
            for (int qq = 0; qq < 4; qq++) {
                float v0 = RELU ? fmaxf(xs0[qq], 0.f) : xs0[qq];
                float v1 = RELU ? fmaxf(xs1[qq], 0.f) : xs1[qq];
                unsigned long long a0 = pack2(v0, v0);
                unsigned long long a1 = pack2(v1, v1);
                const unsigned long long* w2 =
                    reinterpret_cast<const unsigned long long*>(W + (kk * 4 + qq) * FOUT);
#pragma unroll
                for (int p = 0; p < P; p++) {
                    unsigned long long wv = w2[p];
                    acc0[p] = ffma2(a0, wv, acc0[p]);
                    acc1[p] = ffma2(a1, wv, acc1[p]);
                }
            }
        }

        float* o0 = (isRel ? y : h) + (size_t)node0 * FOUT + chunk * OCH;
        float outv[OCH];
#pragma unroll
        for (int p = 0; p < P; p++) unpack2(acc0[p], outv[2 * p], outv[2 * p + 1]);
        if constexpr (OCH >= 4) {
#pragma unroll
            for (int j4 = 0; j4 < OCH / 4; j4++)
                reinterpret_cast<float4*>(o0)[j4] =
                    make_float4(outv[j4 * 4], outv[j4 * 4 + 1], outv[j4 * 4 + 2], outv[j4 * 4 + 3]);
        } else {
            *reinterpret_cast<float2*>(o0) = make_float2(outv[0], outv[1]);
        }
        if (has1) {
            float* o1 = (isRel ? y : h) + (size_t)(node0 + 1) * FOUT + chunk * OCH;
#pragma unroll
            for (int p = 0; p < P; p++) unpack2(acc1[p], outv[2 * p], outv[2 * p + 1]);
            if constexpr (OCH >= 4) {
#pragma unroll
                for (int j4 = 0; j4 < OCH / 4; j4++)
                    reinterpret_cast<float4*>(o1)[j4] =
                        make_float4(outv[j4 * 4], outv[j4 * 4 + 1], outv[j4 * 4 + 2], outv[j4 * 4 + 3]);
            } else {
                *reinterpret_cast<float2*>(o1) = make_float2(outv[0], outv[1]);
            }
        }
    }
}

// ---------------------------------------------------------------------------
// Pull aggregation: one warp per node (validated in R5).
// ---------------------------------------------------------------------------
template <int F>
__device__ __forceinline__ void agg_phase(
    const int* __restrict__ row, const int* __restrict__ srcs,
    const float* __restrict__ y, float* __restrict__ h,
    int n, int gtid, int T) {
    constexpr int CH = F / 4;
    constexpr int RPI = 32 / CH;
    constexpr int STEPS = 32 / RPI;
    const int lane = threadIdx.x & 31;
    const int sub = lane / CH;
    const int c = lane % CH;
    const int nw = T >> 5;

    for (int w = gtid >> 5; w < n; w += nw) {
        const int start = __ldg(row + w);
        const int end = __ldg(row + w + 1);
        float4 acc = make_float4(0.f, 0.f, 0.f, 0.f);

        for (int base = start; base < end; base += 32) {
            const int cnt = min(32, end - base);
            int sj = 0;
            if (lane < cnt) sj = srcs[base + lane];
#pragma unroll
            for (int s = 0; s < STEPS; s++) {
                const int idx = s * RPI + sub;
                const int src = __shfl_sync(0xffffffffu, sj, idx);
                if (idx < cnt) {
                    float4 v = __ldg(reinterpret_cast<const float4*>(y + (size_t)src * F + c * 4));
                    acc.x += v.x; acc.y += v.y; acc.z += v.z; acc.w += v.w;
                }
            }
        }
#pragma unroll
        for (int off = 16; off >= CH; off >>= 1) {
            acc.x += __shfl_down_sync(0xffffffffu, acc.x, off);
            acc.y += __shfl_down_sync(0xffffffffu, acc.y, off);
            acc.z += __shfl_down_sync(0xffffffffu, acc.z, off);
            acc.w += __shfl_down_sync(0xffffffffu, acc.w, off);
        }
        if (lane < CH) {
            float4* hp = reinterpret_cast<float4*>(h + (size_t)w * F) + lane;
            float4 r = *hp;
            r.x += acc.x; r.y += acc.y; r.z += acc.z; r.w += acc.w;
            *hp = r;
        }
    }
}

// Layer-3 aggregation (F=2) fused with 2-class softmax.
__device__ __forceinline__ void agg3_softmax_phase(
    const int* __restrict__ row, const int* __restrict__ srcs,
    const float* __restrict__ y, const float* __restrict__ h,
    float* __restrict__ out, int n, int gtid, int T) {
    const int lane = threadIdx.x & 31;
    const int nw = T >> 5;
    for (int w = gtid >> 5; w < n; w += nw) {
        const int start = __ldg(row + w);
        const int end = __ldg(row + w + 1);
        float ax = 0.f, ay = 0.f;
        for (int i = start + lane; i < end; i += 32) {
            int src = srcs[i];
            float2 v = __ldg(reinterpret_cast<const float2*>(y + 2 * (size_t)src));
            ax += v.x; ay += v.y;
        }
#pragma unroll
        for (int off = 16; off > 0; off >>= 1) {
            ax += __shfl_down_sync(0xffffffffu, ax, off);
            ay += __shfl_down_sync(0xffffffffu, ay, off);
        }
        if (lane == 0) {
            float2 r = *reinterpret_cast<const float2*>(h + 2 * (size_t)w);
            float vx = r.x + ax, vy = r.y + ay;
            float m = fmaxf(vx, vy);
            float ea = __expf(vx - m);
            float eb = __expf(vy - m);
            float inv = 1.0f / (ea + eb);
            reinterpret_cast<float2*>(out)[w] = make_float2(ea * inv, eb * inv);
        }
    }
}

// ---------------------------------------------------------------------------
// One persistent kernel: CSR build + 3 layers + softmax, 9 grid barriers.
// ---------------------------------------------------------------------------
__global__ void __launch_bounds__(TPB, 4)
gnn_persistent(const float* __restrict__ z, const int* __restrict__ ei,
               const float* __restrict__ Wrel1, const float* __restrict__ Wroot1, const float* __restrict__ b1,
               const float* __restrict__ Wrel2, const float* __restrict__ Wroot2, const float* __restrict__ b2,
               const float* __restrict__ Wrel3, const float* __restrict__ Wroot3, const float* __restrict__ b3,
               float* __restrict__ out, int n, int e, int nseg) {
    __shared__ __align__(16) float s_w[2 * 64 * F1 + F1];   // 16.5 KB; aliased by scans
    const int T = gridDim.x * blockDim.x;
    const int gtid = blockIdx.x * blockDim.x + threadIdx.x;

    // A: zero histogram + layer-1 transform (independent work, one phase)
    for (int i = gtid; i < n; i += T) g_cnt[i] = 0;
    transform_phase<64, F1, false>(z, Wrel1, Wroot1, b1, g_y1, g_h1, n, s_w, gtid, T);
    grid_sync();

    // B: in-degree histogram
    for (int t = gtid; t < e; t += T)
        atomicAdd(&g_cnt[__ldg(ei + e + t)], 1);
    grid_sync();

    // C: per-segment sums -> g_bsum
    {
        int* s_i = reinterpret_cast<int*>(s_w);
        for (int seg = blockIdx.x; seg < nseg; seg += gridDim.x) {
            int i = seg * SEG + threadIdx.x;
            int v = (i < n) ? g_cnt[i] : 0;
            s_i[threadIdx.x] = v;
            __syncthreads();
            for (int off = TPB / 2; off > 0; off >>= 1) {
                if (threadIdx.x < off) s_i[threadIdx.x] += s_i[threadIdx.x + off];
                __syncthreads();
            }
            if (threadIdx.x == 0) g_bsum[seg] = s_i[0];
            __syncthreads();
        }
    }
    grid_sync();

    // E: each block locally scans the spine (no global spine phase/barrier),
    // then does per-segment exclusive scans -> row offsets + fill cursors.
    {
        int* s_i = reinterpret_cast<int*>(s_w);                 // [0, TPB) scratch
        int* s_sp = reinterpret_cast<int*>(s_w) + TPB + 32;     // [0, MAX_SEGN) local spine
        if (threadIdx.x < 32) {
            const int lane = threadIdx.x;
            int vals[16];
            int lsum = 0;
#pragma unroll
            for (int qq = 0; qq < 16; qq++) {
                int idx = lane * 16 + qq;
                vals[qq] = (idx < nseg) ? g_bsum[idx] : 0;
                lsum += vals[qq];
            }
            int inc = lsum;
#pragma unroll
            for (int off = 1; off < 32; off <<= 1) {
                int o = __shfl_up_sync(0xffffffffu, inc, off);
                if (lane >= off) inc += o;
            }
            int run = inc - lsum;  // exclusive prefix of this lane's group
#pragma unroll
            for (int qq = 0; qq < 16; qq++) {
                int idx = lane * 16 + qq;
                if (idx < nseg) s_sp[idx] = run;
                run += vals[qq];
            }
        }
        __syncthreads();

        for (int seg = blockIdx.x; seg < nseg; seg += gridDim.x) {
            int i = seg * SEG + threadIdx.x;
            int v = (i < n) ? g_cnt[i] : 0;
            s_i[threadIdx.x] = v;
            __syncthreads();
            for (int off = 1; off < TPB; off <<= 1) {
                int x = (threadIdx.x >= off) ? s_i[threadIdx.x - off] : 0;
                __syncthreads();
                s_i[threadIdx.x] += x;
                __syncthreads();
            }
            if (i < n) {
                int val = s_sp[seg] + s_i[threadIdx.x] - v;  // exclusive
                g_row[i] = val;
                g_cur[i] = val;
            }
            __syncthreads();
        }
        if (gtid == 0) g_row[n] = e;
    }
    grid_sync();

    // F: bucket fill (CSR columns)
    for (int t = gtid; t < e; t += T) {
        int dst = __ldg(ei + e + t);
        int pos = atomicAdd(&g_cur[dst], 1);
        g_srcs[pos] = __ldg(ei + t);
    }
    grid_sync();

    // Layer 1 aggregation
    agg_phase<F1>(g_row, g_srcs, g_y1, g_h1, n, gtid, T);
    grid_sync();
    // Layer 2
    transform_phase<F1, F2, true>(g_h1, Wrel2, Wroot2, b2, g_y2, g_h2, n, s_w, gtid, T);
    grid_sync();
    agg_phase<F2>(g_row, g_srcs, g_y2, g_h2, n, gtid, T);
    grid_sync();
    // Layer 3 + fused softmax
    transform_phase<F2, F3, true>(g_h2, Wrel3, Wroot3, b3, g_y3, g_h3, n, s_w, gtid, T);
    grid_sync();
    agg3_softmax_phase(g_row, g_srcs, g_y3, g_h3, out, n, gtid, T);
}

extern "C" void kernel_launch(void* const* d_in, const int* in_sizes, int n_in,
                              void* d_out, int out_size) {
    const float* z      = (const float*)d_in[0];
    const int*   ei     = (const int*)d_in[1];   // int32 (JAX x64 disabled)
    const float* Wrel1  = (const float*)d_in[2];
    const float* Wroot1 = (const float*)d_in[3];
    const float* b1     = (const float*)d_in[4];
    const float* Wrel2  = (const float*)d_in[5];
    const float* Wroot2 = (const float*)d_in[6];
    const float* b2     = (const float*)d_in[7];
    const float* Wrel3  = (const float*)d_in[8];
    const float* Wroot3 = (const float*)d_in[9];
    const float* b3     = (const float*)d_in[10];

    const int n = in_sizes[0] / 64;   // 100000
    const int e = in_sizes[1] / 2;    // 1600000
    const int nseg = (n + SEG - 1) / SEG;

    int dev = 0, sm = 0, occ = 0;
    cudaGetDevice(&dev);
    cudaDeviceGetAttribute(&sm, cudaDevAttrMultiProcessorCount, dev);
    cudaOccupancyMaxActiveBlocksPerMultiprocessor(&occ, gnn_persistent, TPB, 0);
    if (occ < 1) occ = 1;
    const int blocks = sm * occ;

    gnn_persistent<<<blocks, TPB>>>(z, ei,
                                    Wrel1, Wroot1, b1,
                                    Wrel2, Wroot2, b2,
                                    Wrel3, Wroot3, b3,
                                    (float*)d_out, n, e, nseg);
}

// round 7
// speedup vs baseline: 1.1933x; 1.1933x over previous
#include <cuda_runtime.h>
#include <cstdint>

#define MAX_NODES 100000
#define F1 32
#define F2 16
#define F3 2

// Scratch (device globals; no allocation allowed)
__device__ __align__(256) float g_y1[MAX_NODES * F1];
__device__ __align__(256) float g_h1[MAX_NODES * F1];
__device__ __align__(256) float g_y2[MAX_NODES * F2];
__device__ __align__(256) float g_h2[MAX_NODES * F2];
__device__ __align__(256) float g_y3[MAX_NODES * F3];
__device__ __align__(256) float g_h3[MAX_NODES * F3];

// ---- packed f32x2 helpers (ptxas never auto-fuses; PTX-only path) ----
__device__ __forceinline__ unsigned long long pack2(float lo, float hi) {
    unsigned long long r;
    asm("mov.b64 %0, {%1, %2};" : "=l"(r) : "f"(lo), "f"(hi));
    return r;
}
__device__ __forceinline__ void unpack2(unsigned long long v, float& lo, float& hi) {
    asm("mov.b64 {%0, %1}, %2;" : "=f"(lo), "=f"(hi) : "l"(v));
}
__device__ __forceinline__ unsigned long long ffma2(
    unsigned long long a, unsigned long long b, unsigned long long c) {
    unsigned long long d;
    asm("fma.rn.f32x2 %0, %1, %2, %3;" : "=l"(d) : "l"(a), "l"(b), "l"(c));
    return d;
}

// ---------------------------------------------------------------------------
// Transform: y = act(x) @ Wrel ; h = act(x) @ Wroot + b.
// Work item = (rel|root, pair of nodes). NODES=2 halves SMEM weight traffic;
// fma.rn.f32x2 halves FMA issue + weight-LDS instruction count.
// ---------------------------------------------------------------------------
template <int FIN, int FOUT, bool RELU>
__global__ void __launch_bounds__(256)
transform_k(const float* __restrict__ x,
            const float* __restrict__ Wrel, const float* __restrict__ Wroot,
            const float* __restrict__ b,
            float* __restrict__ y, float* __restrict__ h, int n) {
    __shared__ __align__(16) float s_w[2 * FIN * FOUT + FOUT];
    constexpr int P = FOUT / 2;   // f32x2 accumulator pairs per node

    for (int i = threadIdx.x; i < FIN * FOUT; i += blockDim.x) {
        s_w[i] = Wrel[i];
        s_w[FIN * FOUT + i] = Wroot[i];
    }
    for (int i = threadIdx.x; i < FOUT; i += blockDim.x)
        s_w[2 * FIN * FOUT + i] = b[i];
    __syncthreads();
    const float* s_b = s_w + 2 * FIN * FOUT;

    const int pairs = (n + 1) >> 1;
    const int item = blockIdx.x * blockDim.x + threadIdx.x;
    if (item >= 2 * pairs) return;
    const bool isRel = item < pairs;
    const int node0 = (isRel ? item : item - pairs) * 2;
    const bool has1 = (node0 + 1) < n;
    const float* W = isRel ? s_w : (s_w + FIN * FOUT);

    unsigned long long acc0[P], acc1[P];
#pragma unroll
    for (int p = 0; p < P; p++) {
        unsigned long long init = isRel ? 0ull : pack2(s_b[2 * p], s_b[2 * p + 1]);
        acc0[p] = init;
        acc1[p] = init;
    }

    const float4* xr0 = reinterpret_cast<const float4*>(x + (size_t)node0 * FIN);
    const float4* xr1 = reinterpret_cast<const float4*>(x + (size_t)(node0 + 1) * FIN);
#pragma unroll
    for (int kk = 0; kk < FIN / 4; kk++) {
        float4 xv0 = __ldg(xr0 + kk);
        float4 xv1 = has1 ? __ldg(xr1 + kk) : make_float4(0.f, 0.f, 0.f, 0.f);
        float xs0[4] = {xv0.x, xv0.y, xv0.z, xv0.w};
        float xs1[4] = {xv1.x, xv1.y, xv1.z, xv1.w};
#pragma unroll
        for (int q = 0; q < 4; q++) {
            float v0 = RELU ? fmaxf(xs0[q], 0.f) : xs0[q];
            float v1 = RELU ? fmaxf(xs1[q], 0.f) : xs1[q];
            unsigned long long a0 = pack2(v0, v0);
            unsigned long long a1 = pack2(v1, v1);
            const unsigned long long* w2 =
                reinterpret_cast<const unsigned long long*>(W + (kk * 4 + q) * FOUT);
#pragma unroll
            for (int p = 0; p < P; p++) {
                unsigned long long wv = w2[p];
                acc0[p] = ffma2(a0, wv, acc0[p]);
                acc1[p] = ffma2(a1, wv, acc1[p]);
            }
        }
    }

    float* o0 = (isRel ? y : h) + (size_t)node0 * FOUT;
    float outv[FOUT];
#pragma unroll
    for (int p = 0; p < P; p++) unpack2(acc0[p], outv[2 * p], outv[2 * p + 1]);
    if constexpr (FOUT >= 4) {
#pragma unroll
        for (int j4 = 0; j4 < FOUT / 4; j4++)
            reinterpret_cast<float4*>(o0)[j4] =
                make_float4(outv[j4 * 4], outv[j4 * 4 + 1], outv[j4 * 4 + 2], outv[j4 * 4 + 3]);
    } else {
        *reinterpret_cast<float2*>(o0) = make_float2(outv[0], outv[1]);
    }
    if (has1) {
        float* o1 = (isRel ? y : h) + (size_t)(node0 + 1) * FOUT;
#pragma unroll
        for (int p = 0; p < P; p++) unpack2(acc1[p], outv[2 * p], outv[2 * p + 1]);
        if constexpr (FOUT >= 4) {
#pragma unroll
            for (int j4 = 0; j4 < FOUT / 4; j4++)
                reinterpret_cast<float4*>(o1)[j4] =
                    make_float4(outv[j4 * 4], outv[j4 * 4 + 1], outv[j4 * 4 + 2], outv[j4 * 4 + 3]);
        } else {
            *reinterpret_cast<float2*>(o1) = make_float2(outv[0], outv[1]);
        }
    }
}

// ---------------------------------------------------------------------------
// Edge scatter (R2 verbatim, measured-good): h[dst] += y[src] via
// red.global.add.v4.f32, F/4 chunk-threads per edge.
// ---------------------------------------------------------------------------
template <int F>
__global__ void scatter_k(const int* __restrict__ ei,
                          const float* __restrict__ y,
                          float* __restrict__ h,
                          int e) {
    constexpr int CH = F / 4;
    int t = blockIdx.x * blockDim.x + threadIdx.x;
    if (t >= e * CH) return;
    int edge = t / CH;
    int c    = t % CH;
    int src = ei[edge];
    int dst = ei[e + edge];
    const float4 v = *reinterpret_cast<const float4*>(y + (size_t)src * F + c * 4);
    float* p = h + (size_t)dst * F + c * 4;
    asm volatile("red.global.add.v4.f32 [%0], {%1, %2, %3, %4};"
                 :: "l"(p), "f"(v.x), "f"(v.y), "f"(v.z), "f"(v.w)
                 : "memory");
}

__global__ void scatter2_k(const int* __restrict__ ei,
                           const float* __restrict__ y,
                           float* __restrict__ h,
                           int e) {
    int t = blockIdx.x * blockDim.x + threadIdx.x;
    if (t >= e) return;
    int src = ei[t];
    int dst = ei[e + t];
    const float2 v = *reinterpret_cast<const float2*>(y + 2 * (size_t)src);
    float* p = h + 2 * (size_t)dst;
    asm volatile("red.global.add.v2.f32 [%0], {%1, %2};"
                 :: "l"(p), "f"(v.x), "f"(v.y)
                 : "memory");
}

// 2-class softmax over h3 -> out.
__global__ void softmax_k(const float* __restrict__ h, float* __restrict__ out, int n) {
    int i = blockIdx.x * blockDim.x + threadIdx.x;
    if (i >= n) return;
    float2 v = *reinterpret_cast<const float2*>(h + 2 * (size_t)i);
    float m  = fmaxf(v.x, v.y);
    float ea = __expf(v.x - m);
    float eb = __expf(v.y - m);
    float inv = 1.0f / (ea + eb);
    reinterpret_cast<float2*>(out)[i] = make_float2(ea * inv, eb * inv);
}

extern "C" void kernel_launch(void* const* d_in, const int* in_sizes, int n_in,
                              void* d_out, int out_size) {
    const float* z      = (const float*)d_in[0];
    const int*   ei     = (const int*)d_in[1];   // int32 (JAX x64 disabled)
    const float* Wrel1  = (const float*)d_in[2];
    const float* Wroot1 = (const float*)d_in[3];
    const float* b1     = (const float*)d_in[4];
    const float* Wrel2  = (const float*)d_in[5];
    const float* Wroot2 = (const float*)d_in[6];
    const float* b2     = (const float*)d_in[7];
    const float* Wrel3  = (const float*)d_in[8];
    const float* Wroot3 = (const float*)d_in[9];
    const float* b3     = (const float*)d_in[10];

    const int n = in_sizes[0] / 64;   // 100000
    const int e = in_sizes[1] / 2;    // 1600000

    float *y1, *h1, *y2, *h2, *y3, *h3;
    cudaGetSymbolAddress((void**)&y1, g_y1);
    cudaGetSymbolAddress((void**)&h1, g_h1);
    cudaGetSymbolAddress((void**)&y2, g_y2);
    cudaGetSymbolAddress((void**)&h2, g_h2);
    cudaGetSymbolAddress((void**)&y3, g_y3);
    cudaGetSymbolAddress((void**)&h3, g_h3);

    const int pairs = (n + 1) / 2;
    const int items = 2 * pairs;
    const int itemBlocks = (items + 255) / 256;

    // Layer 1
    transform_k<64, F1, false><<<itemBlocks, 256>>>(z, Wrel1, Wroot1, b1, y1, h1, n);
    {
        int total = e * (F1 / 4);
        scatter_k<F1><<<(total + 255) / 256, 256>>>(ei, y1, h1, e);
    }
    // Layer 2 (ReLU applied on read of h1)
    transform_k<F1, F2, true><<<itemBlocks, 256>>>(h1, Wrel2, Wroot2, b2, y2, h2, n);
    {
        int total = e * (F2 / 4);
        scatter_k<F2><<<(total + 255) / 256, 256>>>(ei, y2, h2, e);
    }
    // Layer 3
    transform_k<F2, F3, true><<<itemBlocks, 256>>>(h2, Wrel3, Wroot3, b3, y3, h3, n);
    scatter2_k<<<(e + 255) / 256, 256>>>(ei, y3, h3, e);

    // Softmax -> output
    softmax_k<<<(n + 255) / 256, 256>>>(h3, (float*)d_out, n);
}

// round 8
// speedup vs baseline: 1.3051x; 1.0937x over previous
#include <cuda_runtime.h>
#include <cstdint>

#define MAX_NODES 100000
#define F1 32
#define F2 16
#define F3 2

// Scratch (device globals; no allocation allowed)
__device__ __align__(256) float g_y1[MAX_NODES * F1];
__device__ __align__(256) float g_h1[MAX_NODES * F1];
__device__ __align__(256) float g_y2[MAX_NODES * F2];
__device__ __align__(256) float g_h2[MAX_NODES * F2];
__device__ __align__(256) float g_y3[MAX_NODES * F3];
__device__ __align__(256) float g_h3[MAX_NODES * F3];

// ---------------------------------------------------------------------------
// Dense transform (R2 exact — measured-good): for each node,
//   y[node] = act(x[node]) @ Wrel
//   h[node] = act(x[node]) @ Wroot + b
// ---------------------------------------------------------------------------
template <int FIN, int FOUT, bool RELU>
__global__ void transform_k(const float* __restrict__ x,
                            const float* __restrict__ Wrel,
                            const float* __restrict__ Wroot,
                            const float* __restrict__ b,
                            float* __restrict__ y,
                            float* __restrict__ h,
                            int n) {
    __shared__ float s_rel[FIN * FOUT];
    __shared__ float s_root[FIN * FOUT];
    __shared__ float s_b[FOUT];
    for (int i = threadIdx.x; i < FIN * FOUT; i += blockDim.x) {
        s_rel[i]  = Wrel[i];
        s_root[i] = Wroot[i];
    }
    for (int i = threadIdx.x; i < FOUT; i += blockDim.x) s_b[i] = b[i];
    __syncthreads();

    int node = blockIdx.x * blockDim.x + threadIdx.x;
    if (node >= n) return;

    float accR[FOUT];
    float accO[FOUT];
#pragma unroll
    for (int j = 0; j < FOUT; j++) { accR[j] = 0.f; accO[j] = 0.f; }

    const float4* xr = reinterpret_cast<const float4*>(x + (size_t)node * FIN);
#pragma unroll
    for (int kk = 0; kk < FIN / 4; kk++) {
        float4 xv = __ldg(xr + kk);
        float xs[4] = {xv.x, xv.y, xv.z, xv.w};
#pragma unroll
        for (int q = 0; q < 4; q++) {
            float v = RELU ? fmaxf(xs[q], 0.f) : xs[q];
            const int k = kk * 4 + q;
#pragma unroll
            for (int j = 0; j < FOUT; j++) {
                accR[j] = fmaf(v, s_rel[k * FOUT + j], accR[j]);
                accO[j] = fmaf(v, s_root[k * FOUT + j], accO[j]);
            }
        }
    }

    float* yo = y + (size_t)node * FOUT;
    float* ho = h + (size_t)node * FOUT;
#pragma unroll
    for (int j = 0; j < FOUT; j++) {
        yo[j] = accR[j];
        ho[j] = accO[j] + s_b[j];
    }
}

// ---------------------------------------------------------------------------
// Edge scatter, 2 edges per thread for ILP (2 gathers + 2 REDs in flight).
// Lane mapping keeps CH contiguous lanes covering one edge's contiguous row
// chunk, preserving wavefront coalescing of the single-edge version.
// ---------------------------------------------------------------------------
template <int F>
__global__ void scatter_k(const int* __restrict__ ei,
                          const float* __restrict__ y,
                          float* __restrict__ h,
                          int e) {
    constexpr int CH = F / 4;
    int t = blockIdx.x * blockDim.x + threadIdx.x;
    int pe = t / CH;            // edge-pair index
    int c  = t % CH;            // chunk within row
    int e0 = 2 * pe;
    int e1 = e0 + 1;
    if (e0 >= e) return;
    bool has1 = e1 < e;

    // Prefetch all indices first (independent loads).
    int src0 = __ldg(ei + e0);
    int dst0 = __ldg(ei + e + e0);
    int src1 = has1 ? __ldg(ei + e1) : 0;
    int dst1 = has1 ? __ldg(ei + e + e1) : 0;

    // Both gathers in flight.
    float4 v0 = __ldg(reinterpret_cast<const float4*>(y + (size_t)src0 * F + c * 4));
    float4 v1 = has1 ? __ldg(reinterpret_cast<const float4*>(y + (size_t)src1 * F + c * 4))
                     : make_float4(0.f, 0.f, 0.f, 0.f);

    float* p0 = h + (size_t)dst0 * F + c * 4;
    asm volatile("red.global.add.v4.f32 [%0], {%1, %2, %3, %4};"
                 :: "l"(p0), "f"(v0.x), "f"(v0.y), "f"(v0.z), "f"(v0.w)
                 : "memory");
    if (has1) {
        float* p1 = h + (size_t)dst1 * F + c * 4;
        asm volatile("red.global.add.v4.f32 [%0], {%1, %2, %3, %4};"
                     :: "l"(p1), "f"(v1.x), "f"(v1.y), "f"(v1.z), "f"(v1.w)
                     : "memory");
    }
}

// Final layer scatter (F=2): 2 edges per thread, red.v2.
__global__ void scatter2_k(const int* __restrict__ ei,
                           const float* __restrict__ y,
                           float* __restrict__ h,
                           int e) {
    int pe = blockIdx.x * blockDim.x + threadIdx.x;
    int e0 = 2 * pe;
    int e1 = e0 + 1;
    if (e0 >= e) return;
    bool has1 = e1 < e;

    int src0 = __ldg(ei + e0);
    int dst0 = __ldg(ei + e + e0);
    int src1 = has1 ? __ldg(ei + e1) : 0;
    int dst1 = has1 ? __ldg(ei + e + e1) : 0;

    float2 v0 = __ldg(reinterpret_cast<const float2*>(y + 2 * (size_t)src0));
    float2 v1 = has1 ? __ldg(reinterpret_cast<const float2*>(y + 2 * (size_t)src1))
                     : make_float2(0.f, 0.f);

    float* p0 = h + 2 * (size_t)dst0;
    asm volatile("red.global.add.v2.f32 [%0], {%1, %2};"
                 :: "l"(p0), "f"(v0.x), "f"(v0.y)
                 : "memory");
    if (has1) {
        float* p1 = h + 2 * (size_t)dst1;
        asm volatile("red.global.add.v2.f32 [%0], {%1, %2};"
                     :: "l"(p1), "f"(v1.x), "f"(v1.y)
                     : "memory");
    }
}

// 2-class softmax over h3 -> out.
__global__ void softmax_k(const float* __restrict__ h, float* __restrict__ out, int n) {
    int i = blockIdx.x * blockDim.x + threadIdx.x;
    if (i >= n) return;
    float2 v = *reinterpret_cast<const float2*>(h + 2 * (size_t)i);
    float m  = fmaxf(v.x, v.y);
    float ea = __expf(v.x - m);
    float eb = __expf(v.y - m);
    float inv = 1.0f / (ea + eb);
    reinterpret_cast<float2*>(out)[i] = make_float2(ea * inv, eb * inv);
}

extern "C" void kernel_launch(void* const* d_in, const int* in_sizes, int n_in,
                              void* d_out, int out_size) {
    const float* z      = (const float*)d_in[0];
    const int*   ei     = (const int*)d_in[1];   // int32 (JAX x64 disabled)
    const float* Wrel1  = (const float*)d_in[2];
    const float* Wroot1 = (const float*)d_in[3];
    const float* b1     = (const float*)d_in[4];
    const float* Wrel2  = (const float*)d_in[5];
    const float* Wroot2 = (const float*)d_in[6];
    const float* b2     = (const float*)d_in[7];
    const float* Wrel3  = (const float*)d_in[8];
    const float* Wroot3 = (const float*)d_in[9];
    const float* b3     = (const float*)d_in[10];

    const int n = in_sizes[0] / 64;   // 100000
    const int e = in_sizes[1] / 2;    // 1600000

    float *y1, *h1, *y2, *h2, *y3, *h3;
    cudaGetSymbolAddress((void**)&y1, g_y1);
    cudaGetSymbolAddress((void**)&h1, g_h1);
    cudaGetSymbolAddress((void**)&y2, g_y2);
    cudaGetSymbolAddress((void**)&h2, g_h2);
    cudaGetSymbolAddress((void**)&y3, g_y3);
    cudaGetSymbolAddress((void**)&h3, g_h3);

    const int TB = 128;
    const int nodeBlocks = (n + TB - 1) / TB;
    const int ep = (e + 1) / 2;   // edge pairs

    // Layer 1
    transform_k<64, F1, false><<<nodeBlocks, TB>>>(z, Wrel1, Wroot1, b1, y1, h1, n);
    {
        int total = ep * (F1 / 4);
        scatter_k<F1><<<(total + 255) / 256, 256>>>(ei, y1, h1, e);
    }
    // Layer 2 (ReLU applied on read of h1)
    transform_k<F1, F2, true><<<nodeBlocks, TB>>>(h1, Wrel2, Wroot2, b2, y2, h2, n);
    {
        int total = ep * (F2 / 4);
        scatter_k<F2><<<(total + 255) / 256, 256>>>(ei, y2, h2, e);
    }
    // Layer 3
    transform_k<F2, F3, true><<<nodeBlocks, TB>>>(h2, Wrel3, Wroot3, b3, y3, h3, n);
    scatter2_k<<<(ep + 255) / 256, 256>>>(ei, y3, h3, e);

    // Softmax -> output
    softmax_k<<<nodeBlocks, TB>>>(h3, (float*)d_out, n);
}

// round 9
// speedup vs baseline: 1.6272x; 1.2469x over previous
#include <cuda_runtime.h>
#include <cstdint>

#define MAX_NODES 100000
#define F1 32
#define F2 16
#define F3 2

// Scratch (device globals; no allocation allowed)
__device__ __align__(256) float g_y1[MAX_NODES * F1];
__device__ __align__(256) float g_h1[MAX_NODES * F1];
__device__ __align__(256) float g_y2[MAX_NODES * F2];
__device__ __align__(256) float g_h2[MAX_NODES * F2];
__device__ __align__(256) float g_y3[MAX_NODES * F3];
__device__ __align__(256) float g_h3[MAX_NODES * F3];

// ---------------------------------------------------------------------------
// Dense transform: y = act(x) @ Wrel ; h = act(x) @ Wroot + b.
// Weights staged in SMEM and read as explicit float4 (LDS.128) so the LSU
// issues 1/4 the instructions; FMA pipe becomes the sole floor.
// ---------------------------------------------------------------------------
template <int FIN, int FOUT, bool RELU>
__global__ void transform_k(const float* __restrict__ x,
                            const float* __restrict__ Wrel,
                            const float* __restrict__ Wroot,
                            const float* __restrict__ b,
                            float* __restrict__ y,
                            float* __restrict__ h,
                            int n) {
    __shared__ __align__(16) float s_rel[FIN * FOUT];
    __shared__ __align__(16) float s_root[FIN * FOUT];
    __shared__ float s_b[FOUT];
    for (int i = threadIdx.x; i < FIN * FOUT; i += blockDim.x) {
        s_rel[i]  = Wrel[i];
        s_root[i] = Wroot[i];
    }
    for (int i = threadIdx.x; i < FOUT; i += blockDim.x) s_b[i] = b[i];
    __syncthreads();

    int node = blockIdx.x * blockDim.x + threadIdx.x;
    if (node >= n) return;

    float accR[FOUT];
    float accO[FOUT];
#pragma unroll
    for (int j = 0; j < FOUT; j++) { accR[j] = 0.f; accO[j] = 0.f; }

    const float4* xr = reinterpret_cast<const float4*>(x + (size_t)node * FIN);
#pragma unroll
    for (int kk = 0; kk < FIN / 4; kk++) {
        float4 xv = __ldg(xr + kk);
        float xs[4] = {xv.x, xv.y, xv.z, xv.w};
#pragma unroll
        for (int q = 0; q < 4; q++) {
            float v = RELU ? fmaxf(xs[q], 0.f) : xs[q];
            const int k = kk * 4 + q;
            if constexpr (FOUT >= 4) {
#pragma unroll
                for (int j4 = 0; j4 < FOUT / 4; j4++) {
                    float4 wr = *reinterpret_cast<const float4*>(&s_rel[k * FOUT + j4 * 4]);
                    float4 wo = *reinterpret_cast<const float4*>(&s_root[k * FOUT + j4 * 4]);
                    accR[j4 * 4 + 0] = fmaf(v, wr.x, accR[j4 * 4 + 0]);
                    accR[j4 * 4 + 1] = fmaf(v, wr.y, accR[j4 * 4 + 1]);
                    accR[j4 * 4 + 2] = fmaf(v, wr.z, accR[j4 * 4 + 2]);
                    accR[j4 * 4 + 3] = fmaf(v, wr.w, accR[j4 * 4 + 3]);
                    accO[j4 * 4 + 0] = fmaf(v, wo.x, accO[j4 * 4 + 0]);
                    accO[j4 * 4 + 1] = fmaf(v, wo.y, accO[j4 * 4 + 1]);
                    accO[j4 * 4 + 2] = fmaf(v, wo.z, accO[j4 * 4 + 2]);
                    accO[j4 * 4 + 3] = fmaf(v, wo.w, accO[j4 * 4 + 3]);
                }
            } else {
#pragma unroll
                for (int j = 0; j < FOUT; j++) {
                    accR[j] = fmaf(v, s_rel[k * FOUT + j], accR[j]);
                    accO[j] = fmaf(v, s_root[k * FOUT + j], accO[j]);
                }
            }
        }
    }

    float* yo = y + (size_t)node * FOUT;
    float* ho = h + (size_t)node * FOUT;
    if constexpr (FOUT >= 4) {
#pragma unroll
        for (int j4 = 0; j4 < FOUT / 4; j4++) {
            reinterpret_cast<float4*>(yo)[j4] =
                make_float4(accR[j4 * 4], accR[j4 * 4 + 1], accR[j4 * 4 + 2], accR[j4 * 4 + 3]);
            reinterpret_cast<float4*>(ho)[j4] =
                make_float4(accO[j4 * 4] + s_b[j4 * 4],     accO[j4 * 4 + 1] + s_b[j4 * 4 + 1],
                            accO[j4 * 4 + 2] + s_b[j4 * 4 + 2], accO[j4 * 4 + 3] + s_b[j4 * 4 + 3]);
        }
    } else {
#pragma unroll
        for (int j = 0; j < FOUT; j++) {
            yo[j] = accR[j];
            ho[j] = accO[j] + s_b[j];
        }
    }
}

// ---------------------------------------------------------------------------
// Edge scatter, 4 edges per thread for ILP (4 gathers + 4 REDs in flight).
// CH contiguous lanes cover one edge's contiguous row chunk (coalesced).
// ---------------------------------------------------------------------------
template <int F>
__global__ void scatter_k(const int* __restrict__ ei,
                          const float* __restrict__ y,
                          float* __restrict__ h,
                          int e) {
    constexpr int CH = F / 4;
    int t = blockIdx.x * blockDim.x + threadIdx.x;
    int pe = t / CH;            // edge-quad index
    int c  = t % CH;            // chunk within row
    int base = 4 * pe;
    if (base >= e) return;

    int src[4], dst[4];
#pragma unroll
    for (int i = 0; i < 4; i++) {
        int eid = base + i;
        bool ok = eid < e;
        src[i] = ok ? __ldg(ei + eid) : 0;
        dst[i] = ok ? __ldg(ei + e + eid) : -1;
    }
    float4 v[4];
#pragma unroll
    for (int i = 0; i < 4; i++) {
        v[i] = (dst[i] >= 0)
             ? __ldg(reinterpret_cast<const float4*>(y + (size_t)src[i] * F + c * 4))
             : make_float4(0.f, 0.f, 0.f, 0.f);
    }
#pragma unroll
    for (int i = 0; i < 4; i++) {
        if (dst[i] >= 0) {
            float* p = h + (size_t)dst[i] * F + c * 4;
            asm volatile("red.global.add.v4.f32 [%0], {%1, %2, %3, %4};"
                         :: "l"(p), "f"(v[i].x), "f"(v[i].y), "f"(v[i].z), "f"(v[i].w)
                         : "memory");
        }
    }
}

// Final layer scatter (F=2): 4 edges per thread, red.v2.
__global__ void scatter2_k(const int* __restrict__ ei,
                           const float* __restrict__ y,
                           float* __restrict__ h,
                           int e) {
    int pe = blockIdx.x * blockDim.x + threadIdx.x;
    int base = 4 * pe;
    if (base >= e) return;

    int src[4], dst[4];
#pragma unroll
    for (int i = 0; i < 4; i++) {
        int eid = base + i;
        bool ok = eid < e;
        src[i] = ok ? __ldg(ei + eid) : 0;
        dst[i] = ok ? __ldg(ei + e + eid) : -1;
    }
    float2 v[4];
#pragma unroll
    for (int i = 0; i < 4; i++) {
        v[i] = (dst[i] >= 0)
             ? __ldg(reinterpret_cast<const float2*>(y + 2 * (size_t)src[i]))
             : make_float2(0.f, 0.f);
    }
#pragma unroll
    for (int i = 0; i < 4; i++) {
        if (dst[i] >= 0) {
            float* p = h + 2 * (size_t)dst[i];
            asm volatile("red.global.add.v2.f32 [%0], {%1, %2};"
                         :: "l"(p), "f"(v[i].x), "f"(v[i].y)
                         : "memory");
        }
    }
}

// 2-class softmax over h3 -> out.
__global__ void softmax_k(const float* __restrict__ h, float* __restrict__ out, int n) {
    int i = blockIdx.x * blockDim.x + threadIdx.x;
    if (i >= n) return;
    float2 v = *reinterpret_cast<const float2*>(h + 2 * (size_t)i);
    float m  = fmaxf(v.x, v.y);
    float ea = __expf(v.x - m);
    float eb = __expf(v.y - m);
    float inv = 1.0f / (ea + eb);
    reinterpret_cast<float2*>(out)[i] = make_float2(ea * inv, eb * inv);
}

extern "C" void kernel_launch(void* const* d_in, const int* in_sizes, int n_in,
                              void* d_out, int out_size) {
    const float* z      = (const float*)d_in[0];
    const int*   ei     = (const int*)d_in[1];   // int32 (JAX x64 disabled)
    const float* Wrel1  = (const float*)d_in[2];
    const float* Wroot1 = (const float*)d_in[3];
    const float* b1     = (const float*)d_in[4];
    const float* Wrel2  = (const float*)d_in[5];
    const float* Wroot2 = (const float*)d_in[6];
    const float* b2     = (const float*)d_in[7];
    const float* Wrel3  = (const float*)d_in[8];
    const float* Wroot3 = (const float*)d_in[9];
    const float* b3     = (const float*)d_in[10];

    const int n = in_sizes[0] / 64;   // 100000
    const int e = in_sizes[1] / 2;    // 1600000

    float *y1, *h1, *y2, *h2, *y3, *h3;
    cudaGetSymbolAddress((void**)&y1, g_y1);
    cudaGetSymbolAddress((void**)&h1, g_h1);
    cudaGetSymbolAddress((void**)&y2, g_y2);
    cudaGetSymbolAddress((void**)&h2, g_h2);
    cudaGetSymbolAddress((void**)&y3, g_y3);
    cudaGetSymbolAddress((void**)&h3, g_h3);

    const int TB = 128;
    const int nodeBlocks = (n + TB - 1) / TB;
    const int eq = (e + 3) / 4;   // edge quads

    // Layer 1
    transform_k<64, F1, false><<<nodeBlocks, TB>>>(z, Wrel1, Wroot1, b1, y1, h1, n);
    {
        int total = eq * (F1 / 4);
        scatter_k<F1><<<(total + 255) / 256, 256>>>(ei, y1, h1, e);
    }
    // Layer 2 (ReLU applied on read of h1)
    transform_k<F1, F2, true><<<nodeBlocks, TB>>>(h1, Wrel2, Wroot2, b2, y2, h2, n);
    {
        int total = eq * (F2 / 4);
        scatter_k<F2><<<(total + 255) / 256, 256>>>(ei, y2, h2, e);
    }
    // Layer 3
    transform_k<F2, F3, true><<<nodeBlocks, TB>>>(h2, Wrel3, Wroot3, b3, y3, h3, n);
    scatter2_k<<<((eq) + 255) / 256, 256>>>(ei, y3, h3, e);

    // Softmax -> output
    softmax_k<<<nodeBlocks, TB>>>(h3, (float*)d_out, n);
}

// round 10
// speedup vs baseline: 1.6510x; 1.0146x over previous
#include <cuda_runtime.h>
#include <cstdint>

#define MAX_NODES 100000
#define F1 32
#define F2 16
#define F3 2

// Scratch (device globals; no allocation allowed)
__device__ __align__(256) float g_y1[MAX_NODES * F1];
__device__ __align__(256) float g_h1[MAX_NODES * F1];
__device__ __align__(256) float g_y2[MAX_NODES * F2];
__device__ __align__(256) float g_h2[MAX_NODES * F2];
__device__ __align__(256) float g_y3[MAX_NODES * F3];
__device__ __align__(256) float g_h3[MAX_NODES * F3];

// ---- packed f32x2 helpers (ptxas never auto-fuses; PTX-only path) ----
__device__ __forceinline__ unsigned long long pack2(float lo, float hi) {
    unsigned long long r;
    asm("mov.b64 %0, {%1, %2};" : "=l"(r) : "f"(lo), "f"(hi));
    return r;
}
__device__ __forceinline__ void unpack2(unsigned long long v, float& lo, float& hi) {
    asm("mov.b64 {%0, %1}, %2;" : "=f"(lo), "=f"(hi) : "l"(v));
}
__device__ __forceinline__ unsigned long long ffma2(
    unsigned long long a, unsigned long long b, unsigned long long c) {
    unsigned long long d;
    asm("fma.rn.f32x2 %0, %1, %2, %3;" : "=l"(d) : "l"(a), "l"(b), "l"(c));
    return d;
}

// ---------------------------------------------------------------------------
// Dense transform (R9 structure + FFMA2 accumulators):
//   y[node] = act(x[node]) @ Wrel ; h[node] = act(x[node]) @ Wroot + b
// Same thread computes rel+root for one node (x read once). Accumulators are
// packed f32x2; weights read as ulonglong2 (LDS.128 broadcast). One
// pack2(v,v) MOV per k-step replaces half of all FMA issue slots.
// ---------------------------------------------------------------------------
template <int FIN, int FOUT, bool RELU>
__global__ void transform_k(const float* __restrict__ x,
                            const float* __restrict__ Wrel,
                            const float* __restrict__ Wroot,
                            const float* __restrict__ b,
                            float* __restrict__ y,
                            float* __restrict__ h,
                            int n) {
    __shared__ __align__(16) float s_rel[FIN * FOUT];
    __shared__ __align__(16) float s_root[FIN * FOUT];
    __shared__ float s_b[FOUT];
    for (int i = threadIdx.x; i < FIN * FOUT; i += blockDim.x) {
        s_rel[i]  = Wrel[i];
        s_root[i] = Wroot[i];
    }
    for (int i = threadIdx.x; i < FOUT; i += blockDim.x) s_b[i] = b[i];
    __syncthreads();

    int node = blockIdx.x * blockDim.x + threadIdx.x;
    if (node >= n) return;

    constexpr int P = FOUT / 2;   // f32x2 pairs
    unsigned long long accR[P], accO[P];
#pragma unroll
    for (int p = 0; p < P; p++) { accR[p] = 0ull; accO[p] = 0ull; }

    const float4* xr = reinterpret_cast<const float4*>(x + (size_t)node * FIN);
#pragma unroll
    for (int kk = 0; kk < FIN / 4; kk++) {
        float4 xv = __ldg(xr + kk);
        float xs[4] = {xv.x, xv.y, xv.z, xv.w};
#pragma unroll
        for (int q = 0; q < 4; q++) {
            float v = RELU ? fmaxf(xs[q], 0.f) : xs[q];
            unsigned long long a = pack2(v, v);
            const int k = kk * 4 + q;
            if constexpr (FOUT >= 4) {
#pragma unroll
                for (int j4 = 0; j4 < FOUT / 4; j4++) {
                    ulonglong2 wr = *reinterpret_cast<const ulonglong2*>(&s_rel[k * FOUT + j4 * 4]);
                    ulonglong2 wo = *reinterpret_cast<const ulonglong2*>(&s_root[k * FOUT + j4 * 4]);
                    accR[j4 * 2 + 0] = ffma2(a, wr.x, accR[j4 * 2 + 0]);
                    accR[j4 * 2 + 1] = ffma2(a, wr.y, accR[j4 * 2 + 1]);
                    accO[j4 * 2 + 0] = ffma2(a, wo.x, accO[j4 * 2 + 0]);
                    accO[j4 * 2 + 1] = ffma2(a, wo.y, accO[j4 * 2 + 1]);
                }
            } else {
                unsigned long long wr = *reinterpret_cast<const unsigned long long*>(&s_rel[k * FOUT]);
                unsigned long long wo = *reinterpret_cast<const unsigned long long*>(&s_root[k * FOUT]);
                accR[0] = ffma2(a, wr, accR[0]);
                accO[0] = ffma2(a, wo, accO[0]);
            }
        }
    }

    float* yo = y + (size_t)node * FOUT;
    float* ho = h + (size_t)node * FOUT;
    float outR[FOUT], outO[FOUT];
#pragma unroll
    for (int p = 0; p < P; p++) {
        unpack2(accR[p], outR[2 * p], outR[2 * p + 1]);
        unpack2(accO[p], outO[2 * p], outO[2 * p + 1]);
    }
    if constexpr (FOUT >= 4) {
#pragma unroll
        for (int j4 = 0; j4 < FOUT / 4; j4++) {
            reinterpret_cast<float4*>(yo)[j4] =
                make_float4(outR[j4 * 4], outR[j4 * 4 + 1], outR[j4 * 4 + 2], outR[j4 * 4 + 3]);
            reinterpret_cast<float4*>(ho)[j4] =
                make_float4(outO[j4 * 4] + s_b[j4 * 4],         outO[j4 * 4 + 1] + s_b[j4 * 4 + 1],
                            outO[j4 * 4 + 2] + s_b[j4 * 4 + 2], outO[j4 * 4 + 3] + s_b[j4 * 4 + 3]);
        }
    } else {
        *reinterpret_cast<float2*>(yo) = make_float2(outR[0], outR[1]);
        *reinterpret_cast<float2*>(ho) = make_float2(outO[0] + s_b[0], outO[1] + s_b[1]);
    }
}

// ---------------------------------------------------------------------------
// Edge scatter (R9 exact — measured-good): 4 edges per thread for ILP.
// ---------------------------------------------------------------------------
template <int F>
__global__ void scatter_k(const int* __restrict__ ei,
                          const float* __restrict__ y,
                          float* __restrict__ h,
                          int e) {
    constexpr int CH = F / 4;
    int t = blockIdx.x * blockDim.x + threadIdx.x;
    int pe = t / CH;            // edge-quad index
    int c  = t % CH;            // chunk within row
    int base = 4 * pe;
    if (base >= e) return;

    int src[4], dst[4];
#pragma unroll
    for (int i = 0; i < 4; i++) {
        int eid = base + i;
        bool ok = eid < e;
        src[i] = ok ? __ldg(ei + eid) : 0;
        dst[i] = ok ? __ldg(ei + e + eid) : -1;
    }
    float4 v[4];
#pragma unroll
    for (int i = 0; i < 4; i++) {
        v[i] = (dst[i] >= 0)
             ? __ldg(reinterpret_cast<const float4*>(y + (size_t)src[i] * F + c * 4))
             : make_float4(0.f, 0.f, 0.f, 0.f);
    }
#pragma unroll
    for (int i = 0; i < 4; i++) {
        if (dst[i] >= 0) {
            float* p = h + (size_t)dst[i] * F + c * 4;
            asm volatile("red.global.add.v4.f32 [%0], {%1, %2, %3, %4};"
                         :: "l"(p), "f"(v[i].x), "f"(v[i].y), "f"(v[i].z), "f"(v[i].w)
                         : "memory");
        }
    }
}

// Final layer scatter (F=2): 4 edges per thread, red.v2.
__global__ void scatter2_k(const int* __restrict__ ei,
                           const float* __restrict__ y,
                           float* __restrict__ h,
                           int e) {
    int pe = blockIdx.x * blockDim.x + threadIdx.x;
    int base = 4 * pe;
    if (base >= e) return;

    int src[4], dst[4];
#pragma unroll
    for (int i = 0; i < 4; i++) {
        int eid = base + i;
        bool ok = eid < e;
        src[i] = ok ? __ldg(ei + eid) : 0;
        dst[i] = ok ? __ldg(ei + e + eid) : -1;
    }
    float2 v[4];
#pragma unroll
    for (int i = 0; i < 4; i++) {
        v[i] = (dst[i] >= 0)
             ? __ldg(reinterpret_cast<const float2*>(y + 2 * (size_t)src[i]))
             : make_float2(0.f, 0.f);
    }
#pragma unroll
    for (int i = 0; i < 4; i++) {
        if (dst[i] >= 0) {
            float* p = h + 2 * (size_t)dst[i];
            asm volatile("red.global.add.v2.f32 [%0], {%1, %2};"
                         :: "l"(p), "f"(v[i].x), "f"(v[i].y)
                         : "memory");
        }
    }
}

// 2-class softmax over h3 -> out.
__global__ void softmax_k(const float* __restrict__ h, float* __restrict__ out, int n) {
    int i = blockIdx.x * blockDim.x + threadIdx.x;
    if (i >= n) return;
    float2 v = *reinterpret_cast<const float2*>(h + 2 * (size_t)i);
    float m  = fmaxf(v.x, v.y);
    float ea = __expf(v.x - m);
    float eb = __expf(v.y - m);
    float inv = 1.0f / (ea + eb);
    reinterpret_cast<float2*>(out)[i] = make_float2(ea * inv, eb * inv);
}

extern "C" void kernel_launch(void* const* d_in, const int* in_sizes, int n_in,
                              void* d_out, int out_size) {
    const float* z      = (const float*)d_in[0];
    const int*   ei     = (const int*)d_in[1];   // int32 (JAX x64 disabled)
    const float* Wrel1  = (const float*)d_in[2];
    const float* Wroot1 = (const float*)d_in[3];
    const float* b1     = (const float*)d_in[4];
    const float* Wrel2  = (const float*)d_in[5];
    const float* Wroot2 = (const float*)d_in[6];
    const float* b2     = (const float*)d_in[7];
    const float* Wrel3  = (const float*)d_in[8];
    const float* Wroot3 = (const float*)d_in[9];
    const float* b3     = (const float*)d_in[10];

    const int n = in_sizes[0] / 64;   // 100000
    const int e = in_sizes[1] / 2;    // 1600000

    float *y1, *h1, *y2, *h2, *y3, *h3;
    cudaGetSymbolAddress((void**)&y1, g_y1);
    cudaGetSymbolAddress((void**)&h1, g_h1);
    cudaGetSymbolAddress((void**)&y2, g_y2);
    cudaGetSymbolAddress((void**)&h2, g_h2);
    cudaGetSymbolAddress((void**)&y3, g_y3);
    cudaGetSymbolAddress((void**)&h3, g_h3);

    const int TB = 128;
    const int nodeBlocks = (n + TB - 1) / TB;
    const int eq = (e + 3) / 4;   // edge quads

    // Layer 1
    transform_k<64, F1, false><<<nodeBlocks, TB>>>(z, Wrel1, Wroot1, b1, y1, h1, n);
    {
        int total = eq * (F1 / 4);
        scatter_k<F1><<<(total + 255) / 256, 256>>>(ei, y1, h1, e);
    }
    // Layer 2 (ReLU applied on read of h1)
    transform_k<F1, F2, true><<<nodeBlocks, TB>>>(h1, Wrel2, Wroot2, b2, y2, h2, n);
    {
        int total = eq * (F2 / 4);
        scatter_k<F2><<<(total + 255) / 256, 256>>>(ei, y2, h2, e);
    }
    // Layer 3
    transform_k<F2, F3, true><<<nodeBlocks, TB>>>(h2, Wrel3, Wroot3, b3, y3, h3, n);
    scatter2_k<<<(eq + 255) / 256, 256>>>(ei, y3, h3, e);

    // Softmax -> output
    softmax_k<<<nodeBlocks, TB>>>(h3, (float*)d_out, n);
}